// round 13
// baseline (speedup 1.0000x reference)
#include <cuda_runtime.h>
#include <cstdint>

// WeightedLoss (adaptive wing + 3x3-dilated weight mask), shape (64,68,128,128) fp32 x2.
// Converged design (measured): grid-stride row-pairs, single wave, spill-free
// max occupancy. This round: 320x5 block shape = 50 warps/SM at exactly 40 regs
// (65536/1600 = 40.96), vs 256x6 = 48 warps/SM. Same reg count, +4% residency.
static constexpr int IMG_ROWS    = 128;
static constexpr int TOTAL_PAIRS = 64 * 68 * (IMG_ROWS / 2);  // 278528 row-pairs
static constexpr int NTHREADS    = 320;
static constexpr int WARPS       = NTHREADS / 32;       // 10 warps/block
static constexpr int NBLK        = 148 * 5;             // 740: one wave, 5 blocks/SM
static constexpr int NWARPS      = NBLK * WARPS;        // 7400 grid-stride warps
static constexpr double TOTAL_ELEMS = 71303168.0;

__device__ double       g_part[NBLK];
__device__ unsigned int g_count = 0;             // self-resetting each launch

__device__ __forceinline__ float ex2a(float x) {
    float y; asm("ex2.approx.f32 %0, %1;" : "=f"(y) : "f"(x)); return y;
}
__device__ __forceinline__ float lg2a(float x) {
    float y; asm("lg2.approx.f32 %0, %1;" : "=f"(y) : "f"(x)); return y;
}

__device__ __forceinline__ float4 max4(float4 a, float4 b) {
    return make_float4(fmaxf(a.x, b.x), fmaxf(a.y, b.y),
                       fmaxf(a.z, b.z), fmaxf(a.w, b.w));
}

// Horizontal 3-max with SAME padding (edge lanes use clipped window).
__device__ __forceinline__ float4 hmax3(float4 v, bool la0, bool la31) {
    float left  = __shfl_up_sync(0xffffffffu, v.w, 1);
    float right = __shfl_down_sync(0xffffffffu, v.x, 1);
    float m01 = fmaxf(v.x, v.y);
    float m12 = fmaxf(v.y, v.z);
    float m23 = fmaxf(v.z, v.w);
    float4 h;
    h.x = la0  ? m01 : fmaxf(left, m01);
    h.y = fmaxf(v.x, m12);
    h.z = fmaxf(v.y, m23);
    h.w = la31 ? m23 : fmaxf(m23, right);
    return h;
}

// Exact rewrite of reference (scaled by 1/14, x14 applied at warp level):
//   loss14 = ln(1+s) + [2*asl*s/(1+s)] * relu
//   s = min(d,0.5)^asl, relu = d - min(d,0.5), asl = 2.1 - l
//   2/(1+s) ~= 1.4815*(1-z)(1+z^2), z = (1+s)/1.35 - 1  (rel err <= 5.6e-5 on
//   the relu-active range s in (0.233,0.467); elsewhere relu == 0).
//   (R8: MUFU rcp regresses; keep the FMA series.)
//   mask: round/dilate/threshold == (max3x3(l) >= 0.1)
__device__ __forceinline__ void elem(float p, float l, float vm,
                                     float& acc, float& accm) {
    float d    = fabsf(p - l);
    float m    = fminf(d, 0.5f);
    float relu = d - m;
    float asl  = 2.1f - l;
    float s    = ex2a(asl * lg2a(m));
    float u    = 1.0f + s;
    float la   = 0.6931471805599453f * lg2a(u);            // ln(1+s)
    float z    = fmaf(u, 0.7407407407407407f, -1.0f);
    float h    = fmaf(z, -1.4814814814814814f, 1.4814814814814814f);
    float t    = fmaf(z * z, h, h);                        // ~= 2/(1+s)
    float loss = fmaf((asl * s) * t, relu, la);
    acc += loss;
    if (vm >= 0.1f) accm += loss;
}

__global__ void __launch_bounds__(NTHREADS, 5)
awing(const float* __restrict__ pred, const float* __restrict__ lmk,
      float* __restrict__ out) {
    const int  lane = threadIdx.x & 31;
    const int  wid  = threadIdx.x >> 5;
    const int  gw   = blockIdx.x * WARPS + wid;
    const bool la0  = (lane == 0), la31 = (lane == 31);

    const float4* lp4 = reinterpret_cast<const float4*>(lmk);
    const float4* pp4 = reinterpret_cast<const float4*>(pred);

    float acc = 0.0f, accm = 0.0f;

#pragma unroll 1
    for (int pair = gw; pair < TOTAL_PAIRS; pair += NWARPS) {
        const int r  = (pair & 63) * 2;             // even row within image
        const int f0 = pair * 64 + lane;            // float4 idx of row r
        const int f1 = f0 + 32;                     // row r+1
        const int fu = (r == 0)   ? f0 : f0 - 32;   // row r-1 (SAME padding)
        const int fd = (r == 126) ? f1 : f1 + 32;   // row r+2 (SAME padding)

        float4 lu = lp4[fu];
        float4 l0 = lp4[f0];
        float4 l1 = lp4[f1];
        float4 ld = lp4[fd];
        float4 p0 = __ldlu(pp4 + f0);               // read-once: last-use hint
        float4 p1 = __ldlu(pp4 + f1);

        float4 m01 = max4(l0, l1);                  // shared middle
        float4 ha  = hmax3(max4(lu, m01), la0, la31);   // 3x3 max, row r
        float4 hb  = hmax3(max4(m01, ld), la0, la31);   // 3x3 max, row r+1

        elem(p0.x, l0.x, ha.x, acc, accm);
        elem(p0.y, l0.y, ha.y, acc, accm);
        elem(p0.z, l0.z, ha.z, acc, accm);
        elem(p0.w, l0.w, ha.w, acc, accm);
        elem(p1.x, l1.x, hb.x, acc, accm);
        elem(p1.y, l1.y, hb.y, acc, accm);
        elem(p1.z, l1.z, hb.z, acc, accm);
        elem(p1.w, l1.w, hb.w, acc, accm);
    }

    float tot = fmaf(accm, 10.0f, acc) * 14.0f;
#pragma unroll
    for (int o = 16; o; o >>= 1)
        tot += __shfl_xor_sync(0xffffffffu, tot, o);

    __shared__ float  wsum[WARPS];
    __shared__ double wsum2[WARPS];
    __shared__ bool   isLast;
    if (lane == 0) wsum[wid] = tot;
    __syncthreads();
    if (threadIdx.x == 0) {
        double s = 0.0;
#pragma unroll
        for (int i = 0; i < WARPS; ++i) s += (double)wsum[i];
        g_part[blockIdx.x] = s;
        __threadfence();
        unsigned int old = atomicAdd(&g_count, 1u);
        isLast = (old == (unsigned)(NBLK - 1));
        if (isLast) g_count = 0;             // reset for next graph replay
    }
    __syncthreads();

    if (isLast) {
        // Deterministic: fixed grid-stride partial order per thread, fixed
        // xor-tree within warp, fixed 10-term sum across warps.
        double s = 0.0;
        for (int i = threadIdx.x; i < NBLK; i += NTHREADS)
            s += __ldcg(&g_part[i]);
#pragma unroll
        for (int o = 16; o; o >>= 1)
            s += __shfl_xor_sync(0xffffffffu, s, o);
        if (lane == 0) wsum2[wid] = s;
        __syncthreads();
        if (threadIdx.x == 0) {
            double t = 0.0;
#pragma unroll
            for (int i = 0; i < WARPS; ++i) t += wsum2[i];
            out[0] = (float)(t * (1.0 / TOTAL_ELEMS));
        }
    }
}

extern "C" void kernel_launch(void* const* d_in, const int* in_sizes, int n_in,
                              void* d_out, int out_size) {
    const float* pred = (const float*)d_in[0];
    const float* lmk  = (const float*)d_in[1];
    awing<<<NBLK, NTHREADS>>>(pred, lmk, (float*)d_out);
}

// round 14
// speedup vs baseline: 1.4574x; 1.4574x over previous
#include <cuda_runtime.h>
#include <cstdint>

// WeightedLoss (adaptive wing + 3x3-dilated weight mask), shape (64,68,128,128) fp32 x2.
// FINAL kernel — 92.7 us (reproduced 4x), DRAM 78%, 6.2 TB/s effective.
// Measured design boundary (every neighbor configuration regresses):
//  - 256x6 = 48 warps/SM is the spill-free occupancy MAXIMUM: 256x7 forces
//    32 regs -> spill -> 121 us (R9); 320x5 also forces 32 regs (per-warp
//    alloc granularity) -> spill -> 136 us (R13). Keep 40 regs / 888 blocks.
//  - row-pair tasks share the vertical max: 6 float4 loads / 2 rows (R7 win).
//  - FMA series for 2/(1+s); MUFU rcp regresses (R8). No prefetch (R5).
//  - fused deterministic last-block reduction (fixed-order, graph-replay safe).
static constexpr int IMG_ROWS    = 128;
static constexpr int TOTAL_PAIRS = 64 * 68 * (IMG_ROWS / 2);  // 278528 row-pairs
static constexpr int WARPS       = 8;
static constexpr int NBLK        = 888;                 // 148 SMs x 6, one wave
static constexpr int NWARPS      = NBLK * WARPS;        // 7104 grid-stride warps
static constexpr double TOTAL_ELEMS = 71303168.0;

__device__ double       g_part[NBLK];
__device__ unsigned int g_count = 0;             // self-resetting each launch

__device__ __forceinline__ float ex2a(float x) {
    float y; asm("ex2.approx.f32 %0, %1;" : "=f"(y) : "f"(x)); return y;
}
__device__ __forceinline__ float lg2a(float x) {
    float y; asm("lg2.approx.f32 %0, %1;" : "=f"(y) : "f"(x)); return y;
}

__device__ __forceinline__ float4 max4(float4 a, float4 b) {
    return make_float4(fmaxf(a.x, b.x), fmaxf(a.y, b.y),
                       fmaxf(a.z, b.z), fmaxf(a.w, b.w));
}

// Horizontal 3-max with SAME padding (edge lanes use clipped window).
__device__ __forceinline__ float4 hmax3(float4 v, bool la0, bool la31) {
    float left  = __shfl_up_sync(0xffffffffu, v.w, 1);
    float right = __shfl_down_sync(0xffffffffu, v.x, 1);
    float m01 = fmaxf(v.x, v.y);
    float m12 = fmaxf(v.y, v.z);
    float m23 = fmaxf(v.z, v.w);
    float4 h;
    h.x = la0  ? m01 : fmaxf(left, m01);
    h.y = fmaxf(v.x, m12);
    h.z = fmaxf(v.y, m23);
    h.w = la31 ? m23 : fmaxf(m23, right);
    return h;
}

// Exact rewrite of reference (scaled by 1/14, x14 applied at warp level):
//   loss14 = ln(1+s) + [2*asl*s/(1+s)] * relu
//   s = min(d,0.5)^asl, relu = d - min(d,0.5), asl = 2.1 - l
//   2/(1+s) ~= 1.4815*(1-z)(1+z^2), z = (1+s)/1.35 - 1  (rel err <= 5.6e-5 on
//   the relu-active range s in (0.233,0.467); elsewhere relu == 0).
//   mask: round/dilate/threshold == (max3x3(l) >= 0.1)
__device__ __forceinline__ void elem(float p, float l, float vm,
                                     float& acc, float& accm) {
    float d    = fabsf(p - l);
    float m    = fminf(d, 0.5f);
    float relu = d - m;
    float asl  = 2.1f - l;
    float s    = ex2a(asl * lg2a(m));
    float u    = 1.0f + s;
    float la   = 0.6931471805599453f * lg2a(u);            // ln(1+s)
    float z    = fmaf(u, 0.7407407407407407f, -1.0f);
    float h    = fmaf(z, -1.4814814814814814f, 1.4814814814814814f);
    float t    = fmaf(z * z, h, h);                        // ~= 2/(1+s)
    float loss = fmaf((asl * s) * t, relu, la);
    acc += loss;
    if (vm >= 0.1f) accm += loss;
}

__global__ void __launch_bounds__(256, 6)
awing(const float* __restrict__ pred, const float* __restrict__ lmk,
      float* __restrict__ out) {
    const int  lane = threadIdx.x & 31;
    const int  wid  = threadIdx.x >> 5;
    const int  gw   = blockIdx.x * WARPS + wid;
    const bool la0  = (lane == 0), la31 = (lane == 31);

    const float4* lp4 = reinterpret_cast<const float4*>(lmk);
    const float4* pp4 = reinterpret_cast<const float4*>(pred);

    float acc = 0.0f, accm = 0.0f;

#pragma unroll 1
    for (int pair = gw; pair < TOTAL_PAIRS; pair += NWARPS) {
        const int r  = (pair & 63) * 2;             // even row within image
        const int f0 = pair * 64 + lane;            // float4 idx of row r
        const int f1 = f0 + 32;                     // row r+1
        const int fu = (r == 0)   ? f0 : f0 - 32;   // row r-1 (SAME padding)
        const int fd = (r == 126) ? f1 : f1 + 32;   // row r+2 (SAME padding)

        float4 lu = lp4[fu];
        float4 l0 = lp4[f0];
        float4 l1 = lp4[f1];
        float4 ld = lp4[fd];
        float4 p0 = __ldlu(pp4 + f0);               // read-once: last-use hint
        float4 p1 = __ldlu(pp4 + f1);

        float4 m01 = max4(l0, l1);                  // shared middle
        float4 ha  = hmax3(max4(lu, m01), la0, la31);   // 3x3 max, row r
        float4 hb  = hmax3(max4(m01, ld), la0, la31);   // 3x3 max, row r+1

        elem(p0.x, l0.x, ha.x, acc, accm);
        elem(p0.y, l0.y, ha.y, acc, accm);
        elem(p0.z, l0.z, ha.z, acc, accm);
        elem(p0.w, l0.w, ha.w, acc, accm);
        elem(p1.x, l1.x, hb.x, acc, accm);
        elem(p1.y, l1.y, hb.y, acc, accm);
        elem(p1.z, l1.z, hb.z, acc, accm);
        elem(p1.w, l1.w, hb.w, acc, accm);
    }

    float tot = fmaf(accm, 10.0f, acc) * 14.0f;
#pragma unroll
    for (int o = 16; o; o >>= 1)
        tot += __shfl_xor_sync(0xffffffffu, tot, o);

    __shared__ float  wsum[WARPS];
    __shared__ double sh[256];
    __shared__ bool   isLast;
    if (lane == 0) wsum[wid] = tot;
    __syncthreads();
    if (threadIdx.x == 0) {
        double s = 0.0;
#pragma unroll
        for (int i = 0; i < WARPS; ++i) s += (double)wsum[i];
        g_part[blockIdx.x] = s;
        __threadfence();
        unsigned int old = atomicAdd(&g_count, 1u);
        isLast = (old == (unsigned)(NBLK - 1));
        if (isLast) g_count = 0;             // reset for next graph replay
    }
    __syncthreads();

    if (isLast) {
        double s = 0.0;
        for (int i = threadIdx.x; i < NBLK; i += 256)
            s += __ldcg(&g_part[i]);
        sh[threadIdx.x] = s;
        __syncthreads();
#pragma unroll
        for (int k = 128; k; k >>= 1) {
            if (threadIdx.x < k) sh[threadIdx.x] += sh[threadIdx.x + k];
            __syncthreads();
        }
        if (threadIdx.x == 0)
            out[0] = (float)(sh[0] * (1.0 / TOTAL_ELEMS));
    }
}

extern "C" void kernel_launch(void* const* d_in, const int* in_sizes, int n_in,
                              void* d_out, int out_size) {
    const float* pred = (const float*)d_in[0];
    const float* lmk  = (const float*)d_in[1];
    awing<<<NBLK, 256>>>(pred, lmk, (float*)d_out);
}

// round 15
// speedup vs baseline: 1.4839x; 1.0182x over previous
#include <cuda_runtime.h>
#include <cstdint>

// WeightedLoss (adaptive wing + 3x3-dilated weight mask), shape (64,68,128,128) fp32 x2.
// Converged kernel — ~92.7 us (reproduced 5x), DRAM ~78%, 6.2 TB/s effective.
// Measured design boundary (every neighbor configuration regresses):
//  - 256x6 = 48 warps/SM is the spill-free occupancy MAXIMUM: 256x7 -> 32 regs
//    spill -> 121 us (R9); 320x5 -> 32 regs spill -> 136 us (R13).
//  - row-pair tasks share the vertical max: 6 float4 loads / 2 rows (R7 win).
//  - FMA series for the reciprocal; MUFU rcp regresses (R8). No prefetch (R5).
//  - R14 shave: accumulate in lg2-units (fold ln2 into series constant and
//    final scale) — removes 1 FMA-pipe op/elem at zero cost.
static constexpr int IMG_ROWS    = 128;
static constexpr int TOTAL_PAIRS = 64 * 68 * (IMG_ROWS / 2);  // 278528 row-pairs
static constexpr int WARPS       = 8;
static constexpr int NBLK        = 888;                 // 148 SMs x 6, one wave
static constexpr int NWARPS      = NBLK * WARPS;        // 7104 grid-stride warps
static constexpr double TOTAL_ELEMS = 71303168.0;

__device__ double       g_part[NBLK];
__device__ unsigned int g_count = 0;             // self-resetting each launch

__device__ __forceinline__ float ex2a(float x) {
    float y; asm("ex2.approx.f32 %0, %1;" : "=f"(y) : "f"(x)); return y;
}
__device__ __forceinline__ float lg2a(float x) {
    float y; asm("lg2.approx.f32 %0, %1;" : "=f"(y) : "f"(x)); return y;
}

__device__ __forceinline__ float4 max4(float4 a, float4 b) {
    return make_float4(fmaxf(a.x, b.x), fmaxf(a.y, b.y),
                       fmaxf(a.z, b.z), fmaxf(a.w, b.w));
}

// Horizontal 3-max with SAME padding (edge lanes use clipped window).
__device__ __forceinline__ float4 hmax3(float4 v, bool la0, bool la31) {
    float left  = __shfl_up_sync(0xffffffffu, v.w, 1);
    float right = __shfl_down_sync(0xffffffffu, v.x, 1);
    float m01 = fmaxf(v.x, v.y);
    float m12 = fmaxf(v.y, v.z);
    float m23 = fmaxf(v.z, v.w);
    float4 h;
    h.x = la0  ? m01 : fmaxf(left, m01);
    h.y = fmaxf(v.x, m12);
    h.z = fmaxf(v.y, m23);
    h.w = la31 ? m23 : fmaxf(m23, right);
    return h;
}

// Exact rewrite of reference, accumulated in lg2-units (x 14*ln2 at the end):
//   lossL = lg2(1+s) + [2*asl*s/((1+s)*ln2)] * relu
//   s = min(d,0.5)^asl, relu = d - min(d,0.5), asl = 2.1 - l
//   2/((1+s)*ln2) ~= 2.13736*(1-z)(1+z^2), z = (1+s)/1.35 - 1  (same series
//   as before with 1/ln2 folded into the constant; rel err <= 5.6e-5 on the
//   relu-active range s in (0.233,0.467); elsewhere relu == 0).
//   (R8: MUFU rcp regresses — serial dep + 4th MUFU. Keep the series.)
//   mask: round/dilate/threshold == (max3x3(l) >= 0.1)
__device__ __forceinline__ void elem(float p, float l, float vm,
                                     float& acc, float& accm) {
    const float K = 2.1373618556764557f;                   // 1.48148.../ln2
    float d    = fabsf(p - l);
    float m    = fminf(d, 0.5f);
    float relu = d - m;
    float asl  = 2.1f - l;
    float s    = ex2a(asl * lg2a(m));
    float u    = 1.0f + s;
    float la   = lg2a(u);                                  // lg2(1+s)
    float z    = fmaf(u, 0.7407407407407407f, -1.0f);
    float h    = fmaf(z, -K, K);
    float t    = fmaf(z * z, h, h);                        // ~= 2/((1+s)ln2)
    float loss = fmaf((asl * s) * t, relu, la);
    acc += loss;
    if (vm >= 0.1f) accm += loss;
}

__global__ void __launch_bounds__(256, 6)
awing(const float* __restrict__ pred, const float* __restrict__ lmk,
      float* __restrict__ out) {
    const int  lane = threadIdx.x & 31;
    const int  wid  = threadIdx.x >> 5;
    const int  gw   = blockIdx.x * WARPS + wid;
    const bool la0  = (lane == 0), la31 = (lane == 31);

    const float4* lp4 = reinterpret_cast<const float4*>(lmk);
    const float4* pp4 = reinterpret_cast<const float4*>(pred);

    float acc = 0.0f, accm = 0.0f;

#pragma unroll 1
    for (int pair = gw; pair < TOTAL_PAIRS; pair += NWARPS) {
        const int r  = (pair & 63) * 2;             // even row within image
        const int f0 = pair * 64 + lane;            // float4 idx of row r
        const int f1 = f0 + 32;                     // row r+1
        const int fu = (r == 0)   ? f0 : f0 - 32;   // row r-1 (SAME padding)
        const int fd = (r == 126) ? f1 : f1 + 32;   // row r+2 (SAME padding)

        float4 lu = lp4[fu];
        float4 l0 = lp4[f0];
        float4 l1 = lp4[f1];
        float4 ld = lp4[fd];
        float4 p0 = __ldlu(pp4 + f0);               // read-once: last-use hint
        float4 p1 = __ldlu(pp4 + f1);

        float4 m01 = max4(l0, l1);                  // shared middle
        float4 ha  = hmax3(max4(lu, m01), la0, la31);   // 3x3 max, row r
        float4 hb  = hmax3(max4(m01, ld), la0, la31);   // 3x3 max, row r+1

        elem(p0.x, l0.x, ha.x, acc, accm);
        elem(p0.y, l0.y, ha.y, acc, accm);
        elem(p0.z, l0.z, ha.z, acc, accm);
        elem(p0.w, l0.w, ha.w, acc, accm);
        elem(p1.x, l1.x, hb.x, acc, accm);
        elem(p1.y, l1.y, hb.y, acc, accm);
        elem(p1.z, l1.z, hb.z, acc, accm);
        elem(p1.w, l1.w, hb.w, acc, accm);
    }

    // 14*ln2 converts lg2-units back to the reference's natural-log loss x14.
    float tot = fmaf(accm, 10.0f, acc) * 9.70406052783923f;
#pragma unroll
    for (int o = 16; o; o >>= 1)
        tot += __shfl_xor_sync(0xffffffffu, tot, o);

    __shared__ float  wsum[WARPS];
    __shared__ double sh[256];
    __shared__ bool   isLast;
    if (lane == 0) wsum[wid] = tot;
    __syncthreads();
    if (threadIdx.x == 0) {
        double s = 0.0;
#pragma unroll
        for (int i = 0; i < WARPS; ++i) s += (double)wsum[i];
        g_part[blockIdx.x] = s;
        __threadfence();
        unsigned int old = atomicAdd(&g_count, 1u);
        isLast = (old == (unsigned)(NBLK - 1));
        if (isLast) g_count = 0;             // reset for next graph replay
    }
    __syncthreads();

    if (isLast) {
        double s = 0.0;
        for (int i = threadIdx.x; i < NBLK; i += 256)
            s += __ldcg(&g_part[i]);
        sh[threadIdx.x] = s;
        __syncthreads();
#pragma unroll
        for (int k = 128; k; k >>= 1) {
            if (threadIdx.x < k) sh[threadIdx.x] += sh[threadIdx.x + k];
            __syncthreads();
        }
        if (threadIdx.x == 0)
            out[0] = (float)(sh[0] * (1.0 / TOTAL_ELEMS));
    }
}

extern "C" void kernel_launch(void* const* d_in, const int* in_sizes, int n_in,
                              void* d_out, int out_size) {
    const float* pred = (const float*)d_in[0];
    const float* lmk  = (const float*)d_in[1];
    awing<<<NBLK, 256>>>(pred, lmk, (float*)d_out);
}

// round 16
// speedup vs baseline: 1.5002x; 1.0110x over previous
#include <cuda_runtime.h>
#include <cstdint>

// WeightedLoss (adaptive wing + 3x3-dilated weight mask), shape (64,68,128,128) fp32 x2.
// FINAL kernel — 91.6 us, DRAM 79.4%, 6.29 TB/s effective (~90% practical ceiling).
// Every design axis is closed by measurement:
//  - 256x6 = 48 warps/SM is the spill-free occupancy MAXIMUM: 256x7 -> 32 regs
//    spill -> 121 us (R9); 320x5 -> 32 regs spill -> 136 us (R13).
//  - row-pair tasks share the vertical max: 6 float4 loads / 2 rows (R7 win).
//  - FMA series for the reciprocal; MUFU rcp regresses (R8). No prefetch (R5).
//  - lg2-unit accumulation folds ln2 into series constant + final scale (R15 win).
//  - 2-term series rejected: error margin too close to the 1e-3 threshold.
static constexpr int IMG_ROWS    = 128;
static constexpr int TOTAL_PAIRS = 64 * 68 * (IMG_ROWS / 2);  // 278528 row-pairs
static constexpr int WARPS       = 8;
static constexpr int NBLK        = 888;                 // 148 SMs x 6, one wave
static constexpr int NWARPS      = NBLK * WARPS;        // 7104 grid-stride warps
static constexpr double TOTAL_ELEMS = 71303168.0;

__device__ double       g_part[NBLK];
__device__ unsigned int g_count = 0;             // self-resetting each launch

__device__ __forceinline__ float ex2a(float x) {
    float y; asm("ex2.approx.f32 %0, %1;" : "=f"(y) : "f"(x)); return y;
}
__device__ __forceinline__ float lg2a(float x) {
    float y; asm("lg2.approx.f32 %0, %1;" : "=f"(y) : "f"(x)); return y;
}

__device__ __forceinline__ float4 max4(float4 a, float4 b) {
    return make_float4(fmaxf(a.x, b.x), fmaxf(a.y, b.y),
                       fmaxf(a.z, b.z), fmaxf(a.w, b.w));
}

// Horizontal 3-max with SAME padding (edge lanes use clipped window).
__device__ __forceinline__ float4 hmax3(float4 v, bool la0, bool la31) {
    float left  = __shfl_up_sync(0xffffffffu, v.w, 1);
    float right = __shfl_down_sync(0xffffffffu, v.x, 1);
    float m01 = fmaxf(v.x, v.y);
    float m12 = fmaxf(v.y, v.z);
    float m23 = fmaxf(v.z, v.w);
    float4 h;
    h.x = la0  ? m01 : fmaxf(left, m01);
    h.y = fmaxf(v.x, m12);
    h.z = fmaxf(v.y, m23);
    h.w = la31 ? m23 : fmaxf(m23, right);
    return h;
}

// Exact rewrite of reference, accumulated in lg2-units (x 14*ln2 at the end):
//   lossL = lg2(1+s) + [2*asl*s/((1+s)*ln2)] * relu
//   s = min(d,0.5)^asl, relu = d - min(d,0.5), asl = 2.1 - l
//   2/((1+s)*ln2) ~= 2.13736*(1-z)(1+z^2), z = (1+s)/1.35 - 1  (rel err
//   <= 5.6e-5 on the relu-active range s in (0.233,0.467); elsewhere relu==0).
//   mask: round/dilate/threshold == (max3x3(l) >= 0.1)
__device__ __forceinline__ void elem(float p, float l, float vm,
                                     float& acc, float& accm) {
    const float K = 2.1373618556764557f;                   // 1.48148.../ln2
    float d    = fabsf(p - l);
    float m    = fminf(d, 0.5f);
    float relu = d - m;
    float asl  = 2.1f - l;
    float s    = ex2a(asl * lg2a(m));
    float u    = 1.0f + s;
    float la   = lg2a(u);                                  // lg2(1+s)
    float z    = fmaf(u, 0.7407407407407407f, -1.0f);
    float h    = fmaf(z, -K, K);
    float t    = fmaf(z * z, h, h);                        // ~= 2/((1+s)ln2)
    float loss = fmaf((asl * s) * t, relu, la);
    acc += loss;
    if (vm >= 0.1f) accm += loss;
}

__global__ void __launch_bounds__(256, 6)
awing(const float* __restrict__ pred, const float* __restrict__ lmk,
      float* __restrict__ out) {
    const int  lane = threadIdx.x & 31;
    const int  wid  = threadIdx.x >> 5;
    const int  gw   = blockIdx.x * WARPS + wid;
    const bool la0  = (lane == 0), la31 = (lane == 31);

    const float4* lp4 = reinterpret_cast<const float4*>(lmk);
    const float4* pp4 = reinterpret_cast<const float4*>(pred);

    float acc = 0.0f, accm = 0.0f;

#pragma unroll 1
    for (int pair = gw; pair < TOTAL_PAIRS; pair += NWARPS) {
        const int r  = (pair & 63) * 2;             // even row within image
        const int f0 = pair * 64 + lane;            // float4 idx of row r
        const int f1 = f0 + 32;                     // row r+1
        const int fu = (r == 0)   ? f0 : f0 - 32;   // row r-1 (SAME padding)
        const int fd = (r == 126) ? f1 : f1 + 32;   // row r+2 (SAME padding)

        float4 lu = lp4[fu];
        float4 l0 = lp4[f0];
        float4 l1 = lp4[f1];
        float4 ld = lp4[fd];
        float4 p0 = __ldlu(pp4 + f0);               // read-once: last-use hint
        float4 p1 = __ldlu(pp4 + f1);

        float4 m01 = max4(l0, l1);                  // shared middle
        float4 ha  = hmax3(max4(lu, m01), la0, la31);   // 3x3 max, row r
        float4 hb  = hmax3(max4(m01, ld), la0, la31);   // 3x3 max, row r+1

        elem(p0.x, l0.x, ha.x, acc, accm);
        elem(p0.y, l0.y, ha.y, acc, accm);
        elem(p0.z, l0.z, ha.z, acc, accm);
        elem(p0.w, l0.w, ha.w, acc, accm);
        elem(p1.x, l1.x, hb.x, acc, accm);
        elem(p1.y, l1.y, hb.y, acc, accm);
        elem(p1.z, l1.z, hb.z, acc, accm);
        elem(p1.w, l1.w, hb.w, acc, accm);
    }

    // 14*ln2 converts lg2-units back to the reference's natural-log loss x14.
    float tot = fmaf(accm, 10.0f, acc) * 9.70406052783923f;
#pragma unroll
    for (int o = 16; o; o >>= 1)
        tot += __shfl_xor_sync(0xffffffffu, tot, o);

    __shared__ float  wsum[WARPS];
    __shared__ double sh[256];
    __shared__ bool   isLast;
    if (lane == 0) wsum[wid] = tot;
    __syncthreads();
    if (threadIdx.x == 0) {
        double s = 0.0;
#pragma unroll
        for (int i = 0; i < WARPS; ++i) s += (double)wsum[i];
        g_part[blockIdx.x] = s;
        __threadfence();
        unsigned int old = atomicAdd(&g_count, 1u);
        isLast = (old == (unsigned)(NBLK - 1));
        if (isLast) g_count = 0;             // reset for next graph replay
    }
    __syncthreads();

    if (isLast) {
        double s = 0.0;
        for (int i = threadIdx.x; i < NBLK; i += 256)
            s += __ldcg(&g_part[i]);
        sh[threadIdx.x] = s;
        __syncthreads();
#pragma unroll
        for (int k = 128; k; k >>= 1) {
            if (threadIdx.x < k) sh[threadIdx.x] += sh[threadIdx.x + k];
            __syncthreads();
        }
        if (threadIdx.x == 0)
            out[0] = (float)(sh[0] * (1.0 / TOTAL_ELEMS));
    }
}

extern "C" void kernel_launch(void* const* d_in, const int* in_sizes, int n_in,
                              void* d_out, int out_size) {
    const float* pred = (const float*)d_in[0];
    const float* lmk  = (const float*)d_in[1];
    awing<<<NBLK, 256>>>(pred, lmk, (float*)d_out);
}

// round 17
// speedup vs baseline: 1.5305x; 1.0202x over previous
#include <cuda_runtime.h>
#include <cstdint>

// WeightedLoss (adaptive wing + 3x3-dilated weight mask), shape (64,68,128,128) fp32 x2.
// Converged design — ~90.6 us, DRAM ~80%, 6.33 TB/s effective.
// Measured boundary (do not revisit): 256x6 = 48 warps/SM spill-free max
// (R9/R13: higher residency forces 32 regs -> spill); row-pair vertical-max
// sharing (R7); no MUFU rcp (R8); no prefetch (R5); lg2-unit accumulation (R15).
// R16 shave: reciprocal via direct Chebyshev quadratic in u — 2 FMAs vs the
// 4-op centered series; minimax rel err <= 1.6e-4 on u in [1.233,1.467].
static constexpr int IMG_ROWS    = 128;
static constexpr int TOTAL_PAIRS = 64 * 68 * (IMG_ROWS / 2);  // 278528 row-pairs
static constexpr int WARPS       = 8;
static constexpr int NBLK        = 888;                 // 148 SMs x 6, one wave
static constexpr int NWARPS      = NBLK * WARPS;        // 7104 grid-stride warps
static constexpr double TOTAL_ELEMS = 71303168.0;

__device__ double       g_part[NBLK];
__device__ unsigned int g_count = 0;             // self-resetting each launch

__device__ __forceinline__ float ex2a(float x) {
    float y; asm("ex2.approx.f32 %0, %1;" : "=f"(y) : "f"(x)); return y;
}
__device__ __forceinline__ float lg2a(float x) {
    float y; asm("lg2.approx.f32 %0, %1;" : "=f"(y) : "f"(x)); return y;
}

__device__ __forceinline__ float4 max4(float4 a, float4 b) {
    return make_float4(fmaxf(a.x, b.x), fmaxf(a.y, b.y),
                       fmaxf(a.z, b.z), fmaxf(a.w, b.w));
}

// Horizontal 3-max with SAME padding (edge lanes use clipped window).
__device__ __forceinline__ float4 hmax3(float4 v, bool la0, bool la31) {
    float left  = __shfl_up_sync(0xffffffffu, v.w, 1);
    float right = __shfl_down_sync(0xffffffffu, v.x, 1);
    float m01 = fmaxf(v.x, v.y);
    float m12 = fmaxf(v.y, v.z);
    float m23 = fmaxf(v.z, v.w);
    float4 h;
    h.x = la0  ? m01 : fmaxf(left, m01);
    h.y = fmaxf(v.x, m12);
    h.z = fmaxf(v.y, m23);
    h.w = la31 ? m23 : fmaxf(m23, right);
    return h;
}

// Exact rewrite of reference, accumulated in lg2-units (x 14*ln2 at the end):
//   lossL = lg2(1+s) + [2*asl*s/((1+s)*ln2)] * relu
//   s = min(d,0.5)^asl, relu = d - min(d,0.5), asl = 2.1 - l
//   2/(u*ln2), u=1+s, via Chebyshev-economized minimax quadratic on the
//   relu-active range u in (1.233, 1.467): rel err <= ~1.6e-4 (elsewhere
//   relu == 0, so the approximation never contributes).
//   mask: round/dilate/threshold == (max3x3(l) >= 0.1)
__device__ __forceinline__ void elem(float p, float l, float vm,
                                     float& acc, float& accm) {
    float d    = fabsf(p - l);
    float m    = fminf(d, 0.5f);
    float relu = d - m;
    float asl  = 2.1f - l;
    float s    = ex2a(asl * lg2a(m));
    float u    = 1.0f + s;
    float la   = lg2a(u);                                  // lg2(1+s)
    float t    = fmaf(u, fmaf(u, 1.181538f, -4.782300f), 6.440045f); // ~2/(u ln2)
    float loss = fmaf((asl * s) * t, relu, la);
    acc += loss;
    if (vm >= 0.1f) accm += loss;
}

__global__ void __launch_bounds__(256, 6)
awing(const float* __restrict__ pred, const float* __restrict__ lmk,
      float* __restrict__ out) {
    const int  lane = threadIdx.x & 31;
    const int  wid  = threadIdx.x >> 5;
    const int  gw   = blockIdx.x * WARPS + wid;
    const bool la0  = (lane == 0), la31 = (lane == 31);

    const float4* lp4 = reinterpret_cast<const float4*>(lmk);
    const float4* pp4 = reinterpret_cast<const float4*>(pred);

    float acc = 0.0f, accm = 0.0f;

#pragma unroll 1
    for (int pair = gw; pair < TOTAL_PAIRS; pair += NWARPS) {
        const int r  = (pair & 63) * 2;             // even row within image
        const int f0 = pair * 64 + lane;            // float4 idx of row r
        const int f1 = f0 + 32;                     // row r+1
        const int fu = (r == 0)   ? f0 : f0 - 32;   // row r-1 (SAME padding)
        const int fd = (r == 126) ? f1 : f1 + 32;   // row r+2 (SAME padding)

        float4 lu = lp4[fu];
        float4 l0 = lp4[f0];
        float4 l1 = lp4[f1];
        float4 ld = lp4[fd];
        float4 p0 = __ldlu(pp4 + f0);               // read-once: last-use hint
        float4 p1 = __ldlu(pp4 + f1);

        float4 m01 = max4(l0, l1);                  // shared middle
        float4 ha  = hmax3(max4(lu, m01), la0, la31);   // 3x3 max, row r
        float4 hb  = hmax3(max4(m01, ld), la0, la31);   // 3x3 max, row r+1

        elem(p0.x, l0.x, ha.x, acc, accm);
        elem(p0.y, l0.y, ha.y, acc, accm);
        elem(p0.z, l0.z, ha.z, acc, accm);
        elem(p0.w, l0.w, ha.w, acc, accm);
        elem(p1.x, l1.x, hb.x, acc, accm);
        elem(p1.y, l1.y, hb.y, acc, accm);
        elem(p1.z, l1.z, hb.z, acc, accm);
        elem(p1.w, l1.w, hb.w, acc, accm);
    }

    // 14*ln2 converts lg2-units back to the reference's natural-log loss x14.
    float tot = fmaf(accm, 10.0f, acc) * 9.70406052783923f;
#pragma unroll
    for (int o = 16; o; o >>= 1)
        tot += __shfl_xor_sync(0xffffffffu, tot, o);

    __shared__ float  wsum[WARPS];
    __shared__ double sh[256];
    __shared__ bool   isLast;
    if (lane == 0) wsum[wid] = tot;
    __syncthreads();
    if (threadIdx.x == 0) {
        double s = 0.0;
#pragma unroll
        for (int i = 0; i < WARPS; ++i) s += (double)wsum[i];
        g_part[blockIdx.x] = s;
        __threadfence();
        unsigned int old = atomicAdd(&g_count, 1u);
        isLast = (old == (unsigned)(NBLK - 1));
        if (isLast) g_count = 0;             // reset for next graph replay
    }
    __syncthreads();

    if (isLast) {
        double s = 0.0;
        for (int i = threadIdx.x; i < NBLK; i += 256)
            s += __ldcg(&g_part[i]);
        sh[threadIdx.x] = s;
        __syncthreads();
#pragma unroll
        for (int k = 128; k; k >>= 1) {
            if (threadIdx.x < k) sh[threadIdx.x] += sh[threadIdx.x + k];
            __syncthreads();
        }
        if (threadIdx.x == 0)
            out[0] = (float)(sh[0] * (1.0 / TOTAL_ELEMS));
    }
}

extern "C" void kernel_launch(void* const* d_in, const int* in_sizes, int n_in,
                              void* d_out, int out_size) {
    const float* pred = (const float*)d_in[0];
    const float* lmk  = (const float*)d_in[1];
    awing<<<NBLK, 256>>>(pred, lmk, (float*)d_out);
}